// round 6
// baseline (speedup 1.0000x reference)
#include <cuda_runtime.h>
#include <math.h>

#define V_NODES 50000
#define E_EDGES 25000
#define NNZ     600000
#define NSUB    8
#define KDIM    16
#define D       128          // NSUB*KDIM
#define NUM_STEP 4
#define EPSF    1e-10f

#define NB       2048        // gather grid blocks (partials sized to this)
#define PSTRIDE  2560        // floats per block partial: 2048 gram + 128 p + 128 sq + 4 ent

// ---------------- persistent device scratch (no allocations allowed) ----------
static __device__ float g_Xbuf[(size_t)V_NODES * D];   // current X (prob values)
static __device__ float g_Yval[(size_t)E_EDGES * D];   // current Y (mean values)
static __device__ int   g_adjE[NNZ];                   // per-edge adjacency: node ids
static __device__ int   g_adjV[NNZ];                   // per-node adjacency: edge ids
static __device__ int   g_offE[E_EDGES];
static __device__ int   g_offV[V_NODES];
static __device__ int   g_curE[E_EDGES];
static __device__ int   g_curV[V_NODES];
static __device__ int   g_cntE[E_EDGES];
static __device__ int   g_cntV[V_NODES];
static __device__ float g_invCntE[E_EDGES];
static __device__ float g_invCntV[V_NODES];
static __device__ float g_part[(size_t)NB * PSTRIDE];  // per-block stat partials
static __device__ float g_pAcc[D];
static __device__ float g_sqAcc[D];
static __device__ float g_gram[D * KDIM];
static __device__ float g_ent;
static __device__ float g_lossLocal;
static __device__ float g_lossGlobal;

// ---------------- init: zero counts + stats + losses ----------------
__global__ void k_init() {
    int i = blockIdx.x * blockDim.x + threadIdx.x;
    int stride = gridDim.x * blockDim.x;
    for (int j = i; j < E_EDGES; j += stride) g_cntE[j] = 0;
    for (int j = i; j < V_NODES; j += stride) g_cntV[j] = 0;
    if (i < D) { g_pAcc[i] = 0.f; g_sqAcc[i] = 0.f; }
    if (i < D * KDIM) g_gram[i] = 0.f;
    if (i == 0) { g_ent = 0.f; g_lossLocal = 0.f; g_lossGlobal = 0.f; }
}

// ---------------- degree counts (step-invariant) ----------------
__global__ void k_counts(const int* __restrict__ Vi, const int* __restrict__ Ei) {
    int i = blockIdx.x * blockDim.x + threadIdx.x;
    if (i < NNZ) {
        atomicAdd(&g_cntE[Ei[i]], 1);
        atomicAdd(&g_cntV[Vi[i]], 1);
    }
}

__global__ void k_invcnt() {
    int i = blockIdx.x * blockDim.x + threadIdx.x;
    if (i < E_EDGES) g_invCntE[i] = 1.f / fmaxf((float)g_cntE[i], 1.f);
    if (i < V_NODES) g_invCntV[i] = 1.f / fmaxf((float)g_cntV[i], 1.f);
}

// ---------------- exclusive prefix scan (block 0: E, block 1: V) ----------------
__global__ void k_scan() {
    const int  n   = (blockIdx.x == 0) ? E_EDGES : V_NODES;
    const int* cnt = (blockIdx.x == 0) ? g_cntE : g_cntV;
    int* off       = (blockIdx.x == 0) ? g_offE : g_offV;
    int* cur       = (blockIdx.x == 0) ? g_curE : g_curV;
    __shared__ int wsum[32];
    __shared__ int s_carry;
    int t = threadIdx.x, lane = t & 31, wid = t >> 5;
    if (t == 0) s_carry = 0;
    __syncthreads();
    for (int basei = 0; basei < n; basei += 1024) {
        int i = basei + t;
        int v = (i < n) ? cnt[i] : 0;
        int x = v;
        #pragma unroll
        for (int o = 1; o < 32; o <<= 1) {
            int y = __shfl_up_sync(0xFFFFFFFFu, x, o);
            if (lane >= o) x += y;
        }
        if (lane == 31) wsum[wid] = x;
        __syncthreads();
        if (wid == 0) {
            int w = wsum[lane];
            #pragma unroll
            for (int o = 1; o < 32; o <<= 1) {
                int y = __shfl_up_sync(0xFFFFFFFFu, w, o);
                if (lane >= o) w += y;
            }
            wsum[lane] = w;
        }
        __syncthreads();
        int wpre = (wid > 0) ? wsum[wid - 1] : 0;
        int incl = x + wpre + s_carry;
        if (i < n) { off[i] = incl - v; cur[i] = incl - v; }
        __syncthreads();
        if (t == 1023) s_carry = incl;
        __syncthreads();
    }
}

// ---------------- CSR fill ----------------
__global__ void k_fill(const int* __restrict__ Vi, const int* __restrict__ Ei) {
    int i = blockIdx.x * blockDim.x + threadIdx.x;
    if (i >= NNZ) return;
    int v = Vi[i], e = Ei[i];
    int pe = atomicAdd(&g_curE[e], 1);
    g_adjE[pe] = v;
    int pv = atomicAdd(&g_curV[v], 1);
    g_adjV[pv] = e;
}

// ---------------- gumbel softmax: X0 = softmax(logits + gumbel) over K ----------
__global__ void k_gumbel(const float* __restrict__ emb, const float* __restrict__ gum) {
    int v = blockIdx.x;
    int t = threadIdx.x;                 // (s = t/16, k = t%16)
    size_t off = (size_t)v * D + t;
    float x = emb[off] + gum[off];       // TAU == 1
    float m = x;
    #pragma unroll
    for (int o = 8; o >= 1; o >>= 1) m = fmaxf(m, __shfl_xor_sync(0xFFFFFFFFu, m, o, 16));
    float e = __expf(x - m);
    float ssum = e;
    #pragma unroll
    for (int o = 8; o >= 1; o >>= 1) ssum += __shfl_xor_sync(0xFFFFFFFFu, ssum, o, 16);
    g_Xbuf[off] = e / ssum;
}

// ---------------- fused gather + mean + stats ----------------
// Block of 128 threads, thread t owns column (s = t/16, i = t%16).
// IS_X=false: Y[e] = mean over incident nodes of X   (E rows)
// IS_X=true : X[v] = mean over incident edges of Y   (V rows)
// Stats (entropy, p-sum, sq-norm, gram) computed on the output rows, written
// as per-block partials (no float atomics -> fast + reproducible reduce order).
template <bool IS_X>
__global__ void __launch_bounds__(128) k_gather() {
    const int nrows = IS_X ? V_NODES : E_EDGES;
    const int* __restrict__ adj   = IS_X ? g_adjV : g_adjE;
    const int* __restrict__ off   = IS_X ? g_offV : g_offE;
    const int* __restrict__ cnt   = IS_X ? g_cntV : g_cntE;
    const float* __restrict__ invc = IS_X ? g_invCntV : g_invCntE;
    const float* __restrict__ src  = IS_X ? g_Yval : g_Xbuf;
    float* __restrict__ dst        = IS_X ? g_Xbuf : g_Yval;

    __shared__ int sh[128];
    int t = threadIdx.x, lane = t & 31, base = lane & 16;
    float pacc = 0.f, sqacc = 0.f, ent = 0.f;
    float gacc[KDIM];
    #pragma unroll
    for (int j = 0; j < KDIM; j++) gacc[j] = 0.f;

    for (int r = blockIdx.x; r < nrows; r += gridDim.x) {
        int o = off[r], c = cnt[r];
        float a0 = 0.f, a1 = 0.f;
        for (int cb = 0; cb < c; cb += 128) {
            int m = min(128, c - cb);
            __syncthreads();
            if (t < m) sh[t] = adj[o + cb + t];
            __syncthreads();
            int j = 0;
            #pragma unroll 4
            for (; j + 2 <= m; j += 2) {
                a0 += src[(size_t)sh[j] * D + t];
                a1 += src[(size_t)sh[j + 1] * D + t];
            }
            if (j < m) a0 += src[(size_t)sh[j] * D + t];
        }
        float y = (a0 + a1) * invc[r];
        dst[(size_t)r * D + t] = y;
        ent   += y * __logf(y + EPSF);
        pacc  += y;
        sqacc += y * y;
        #pragma unroll
        for (int j = 0; j < KDIM; j++)
            gacc[j] += y * __shfl_sync(0xFFFFFFFFu, y, base + j, 32);
    }

    float* part = g_part + (size_t)blockIdx.x * PSTRIDE;
    #pragma unroll
    for (int j = 0; j < KDIM; j++) part[t * KDIM + j] = gacc[j];
    part[2048 + t] = pacc;
    part[2176 + t] = sqacc;
    #pragma unroll
    for (int o2 = 16; o2 >= 1; o2 >>= 1)
        ent += __shfl_xor_sync(0xFFFFFFFFu, ent, o2);
    if (lane == 0) part[2304 + (t >> 5)] = ent;
}

// ---------------- reduce per-block partials into global stats ----------------
// grid (20, NB/32): x covers slots, y covers a 32-block range of partials.
__global__ void k_reduce() {
    int s = blockIdx.x * 128 + threadIdx.x;
    if (s >= 2308) return;
    const float* p = g_part + (size_t)blockIdx.y * 32 * PSTRIDE + s;
    float a = 0.f;
    #pragma unroll 8
    for (int b = 0; b < 32; b++) a += p[(size_t)b * PSTRIDE];
    if (s < 2048)       atomicAdd(&g_gram[s], a);
    else if (s < 2176)  atomicAdd(&g_pAcc[s - 2048], a);
    else if (s < 2304)  atomicAdd(&g_sqAcc[s - 2176], a);
    else                atomicAdd(&g_ent, a);
}

// ---------------- finalize: fold stats into losses, zero stats ----------------
template <int NROWS>
__global__ void k_finalize() {
    int tid  = threadIdx.x;              // 0..127, (s,i)
    int lane = tid & 31;
    int base = lane & 16;
    __shared__ float shA[D], shB[D];

    float invN = 1.f / (float)NROWS;
    float p = g_pAcc[tid] * invN;
    float plogp = p * __logf(p + EPSF);

    float ni = sqrtf(g_sqAcc[tid]);
    float Crow[KDIM];
    float mx = -1e30f;
    #pragma unroll
    for (int j = 0; j < KDIM; j++) {
        float nj = __shfl_sync(0xFFFFFFFFu, ni, base + j, 32);
        float c = g_gram[tid * KDIM + j] / fmaxf(ni * nj, EPSF);
        Crow[j] = c;
        mx = fmaxf(mx, c);
    }
    float se = 0.f;
    #pragma unroll
    for (int j = 0; j < KDIM; j++) se += __expf(Crow[j] - mx);
    float nld = mx + __logf(se) - Crow[tid & 15];   // -log(softmax diag)

    shA[tid] = plogp; shB[tid] = nld;
    __syncthreads();
    #pragma unroll
    for (int s2 = 64; s2 >= 1; s2 >>= 1) {
        if (tid < s2) { shA[tid] += shA[tid + s2]; shB[tid] += shB[tid + s2]; }
        __syncthreads();
    }
    if (tid == 0) {
        // loss_global += -mean_S(-sum_k p log(p+eps)) + discrimination
        g_lossGlobal += shA[0] / (float)NSUB + shB[0] / (float)D;
        // loss_local += mean over (N,S) of -sum_k y log(y+eps)
        g_lossLocal  += -g_ent / ((float)NROWS * (float)NSUB);
        g_ent = 0.f;
    }
    g_pAcc[tid] = 0.f;
    g_sqAcc[tid] = 0.f;
    #pragma unroll
    for (int j = 0; j < KDIM; j++) g_gram[tid * KDIM + j] = 0.f;
}

// ---------------- output ----------------
__global__ void k_out(float* __restrict__ out, int n) {
    int i = blockIdx.x * blockDim.x + threadIdx.x;
    if (i >= n) return;
    float v = 0.f;
    if (i == 0) v = g_lossLocal;
    else if (i == 1) v = g_lossGlobal;
    out[i] = v;
}

// ---------------- launch ----------------
extern "C" void kernel_launch(void* const* d_in, const int* in_sizes, int n_in,
                              void* d_out, int out_size) {
    const float* emb = (const float*)d_in[0];
    const float* gum = (const float*)d_in[1];
    const int*   Vi  = (const int*)d_in[2];
    const int*   Ei  = (const int*)d_in[3];
    float* out = (float*)d_out;

    k_init<<<512, 256>>>();
    k_counts<<<(NNZ + 255) / 256, 256>>>(Vi, Ei);
    k_invcnt<<<(V_NODES + 255) / 256, 256>>>();
    k_scan<<<2, 1024>>>();
    k_fill<<<(NNZ + 255) / 256, 256>>>(Vi, Ei);
    k_gumbel<<<V_NODES, 128>>>(emb, gum);

    dim3 redGrid(20, NB / 32);
    for (int step = 0; step < NUM_STEP; step++) {
        k_gather<false><<<NB, 128>>>();
        k_reduce<<<redGrid, 128>>>();
        k_finalize<E_EDGES><<<1, 128>>>();
        k_gather<true><<<NB, 128>>>();
        k_reduce<<<redGrid, 128>>>();
        k_finalize<V_NODES><<<1, 128>>>();
    }
    k_out<<<1, 256>>>(out, out_size);
}